// round 2
// baseline (speedup 1.0000x reference)
#include <cuda_runtime.h>
#include <cstdint>

#define N_NODES 12288
#define H_DIM   128
#define E_EDGES 393216
#define NEGVAL  (-1000000000.0f)

// Scratch for per-node partial dot products (no cudaMalloc allowed).
__device__ float g_d1[N_NODES];
__device__ float g_d2[N_NODES];

// ---------------------------------------------------------------------------
// Kernel 1 (fused): per-node dots + fill of the 604 MB output with NEG.
//
// Dots: global warp w (< 12288) computes
//   d1[w] = dot(h[w], W[0:H]),  d2[w] = dot(h[w], W[H:2H])
// The 6.3 MB of reads overlap with the store stream and are hidden.
//
// Fill: each block owns a CONTIGUOUS chunk of the output (~255 KB) and walks
// it block-strided, so every iteration the block stores 4 KB contiguous and
// consecutive iterations are adjacent -> good DRAM row-buffer locality.
// ---------------------------------------------------------------------------
__global__ void dots_fill_kernel(const float* __restrict__ h,
                                 const float* __restrict__ W,
                                 float4* __restrict__ out, size_t n4) {
    // ---- dots part (first 12288 global warps) ----
    int gw   = (int)((blockIdx.x * blockDim.x + threadIdx.x) >> 5);
    int lane = threadIdx.x & 31;
    if (gw < N_NODES) {
        const float* hr = h + (size_t)gw * H_DIM;
        float s1 = 0.0f, s2 = 0.0f;
#pragma unroll
        for (int i = 0; i < 4; i++) {
            int c = lane + i * 32;
            float hv = __ldg(&hr[c]);
            s1 = fmaf(hv, __ldg(&W[c]), s1);
            s2 = fmaf(hv, __ldg(&W[H_DIM + c]), s2);
        }
#pragma unroll
        for (int off = 16; off; off >>= 1) {
            s1 += __shfl_down_sync(0xffffffffu, s1, off);
            s2 += __shfl_down_sync(0xffffffffu, s2, off);
        }
        if (lane == 0) {
            g_d1[gw] = s1;
            g_d2[gw] = s2;
        }
    }

    // ---- fill part: contiguous per-block chunk ----
    size_t chunk = (n4 + gridDim.x - 1) / gridDim.x;
    size_t beg   = (size_t)blockIdx.x * chunk;
    size_t end   = beg + chunk;
    if (end > n4) end = n4;

    const float4 v = make_float4(NEGVAL, NEGVAL, NEGVAL, NEGVAL);
    for (size_t i = beg + threadIdx.x; i < end; i += blockDim.x) {
        __stcs(&out[i], v);   // streaming store: evict-first in L2
    }
}

// ---------------------------------------------------------------------------
// Kernel 2: scatter edge values. val = d1[dst] + d2[src] + w*W[2H] + b
// Races on duplicate (dst,src) pairs are benign (rel_err ~1e-14 measured).
// ---------------------------------------------------------------------------
__global__ void scatter_kernel(const int*   __restrict__ src,
                               const int*   __restrict__ dst,
                               const float* __restrict__ wts,
                               const float* __restrict__ W,
                               const float* __restrict__ b,
                               float* __restrict__ out) {
    int e = (int)(blockIdx.x * blockDim.x + threadIdx.x);
    if (e >= E_EDGES) return;
    int s = src[e];
    int d = dst[e];
    float val = g_d1[d] + g_d2[s] + wts[e] * __ldg(&W[2 * H_DIM]) + __ldg(&b[0]);
    out[(size_t)d * N_NODES + s] = val;
}

// ---------------------------------------------------------------------------
// Launch. Input order (metadata): h, sources, dests, weights, W, b
// ---------------------------------------------------------------------------
extern "C" void kernel_launch(void* const* d_in, const int* in_sizes, int n_in,
                              void* d_out, int out_size) {
    const float* h       = (const float*)d_in[0];
    const int*   sources = (const int*)  d_in[1];
    const int*   dests   = (const int*)  d_in[2];
    const float* weights = (const float*)d_in[3];
    const float* W       = (const float*)d_in[4];
    const float* b       = (const float*)d_in[5];
    float*       out     = (float*)d_out;

    // 1) fused dots + fill
    {
        size_t n4   = ((size_t)N_NODES * N_NODES) / 4;  // 37,748,736 float4s
        int threads = 256;                              // 8 warps/block
        int blocks  = 148 * 16;                         // 2368 blocks (>=1536 for dots)
        dots_fill_kernel<<<blocks, threads>>>(h, W, (float4*)out, n4);
    }

    // 2) scatter edges
    {
        int threads = 256;
        int blocks  = (E_EDGES + threads - 1) / threads;  // 1536
        scatter_kernel<<<blocks, threads>>>(sources, dests, weights, W, b, out);
    }
}

// round 3
// speedup vs baseline: 1.0011x; 1.0011x over previous
#include <cuda_runtime.h>
#include <cstdint>

#define N_NODES 12288
#define H_DIM   128
#define E_EDGES 393216
#define NEGVAL  (-1000000000.0f)

// Scratch for per-node partial dot products (no cudaMalloc allowed).
__device__ float g_d1[N_NODES];
__device__ float g_d2[N_NODES];

// ---------------------------------------------------------------------------
// Kernel 1 (fused): per-node dots + fill of the 604 MB output with NEG.
// ---------------------------------------------------------------------------
__global__ void dots_fill_kernel(const float* __restrict__ h,
                                 const float* __restrict__ W,
                                 float4* __restrict__ out, size_t n4) {
    // ---- dots part (first 12288 global warps); 1 float4 load per lane ----
    int gw   = (int)((blockIdx.x * blockDim.x + threadIdx.x) >> 5);
    int lane = threadIdx.x & 31;
    if (gw < N_NODES) {
        const float4* hr4 = (const float4*)(h + (size_t)gw * H_DIM);
        const float4* w14 = (const float4*)(W);
        const float4* w24 = (const float4*)(W + H_DIM);
        float4 hv = __ldg(&hr4[lane]);
        float4 w1 = __ldg(&w14[lane]);
        float4 w2 = __ldg(&w24[lane]);
        float s1 = fmaf(hv.x, w1.x, fmaf(hv.y, w1.y, fmaf(hv.z, w1.z, hv.w * w1.w)));
        float s2 = fmaf(hv.x, w2.x, fmaf(hv.y, w2.y, fmaf(hv.z, w2.z, hv.w * w2.w)));
#pragma unroll
        for (int off = 16; off; off >>= 1) {
            s1 += __shfl_down_sync(0xffffffffu, s1, off);
            s2 += __shfl_down_sync(0xffffffffu, s2, off);
        }
        if (lane == 0) {
            g_d1[gw] = s1;
            g_d2[gw] = s2;
        }
    }

    // ---- fill part: contiguous per-block chunk, streaming stores ----
    size_t chunk = (n4 + gridDim.x - 1) / gridDim.x;
    size_t beg   = (size_t)blockIdx.x * chunk;
    size_t end   = beg + chunk;
    if (end > n4) end = n4;

    const float4 v = make_float4(NEGVAL, NEGVAL, NEGVAL, NEGVAL);
    for (size_t i = beg + threadIdx.x; i < end; i += blockDim.x) {
        __stcs(&out[i], v);
    }
}

// ---------------------------------------------------------------------------
// Kernel 2: scatter, ILP x4. val = d1[dst] + d2[src] + w*W[2H] + b
// All independent loads issued before the dependent gathers (MLP=8/thread).
// __stwt: write-through, no L2 allocation -> don't fight the fill's dirty
// writeback drain. Races on duplicate (dst,src) pairs are benign.
// ---------------------------------------------------------------------------
__global__ void scatter_kernel(const int*   __restrict__ src,
                               const int*   __restrict__ dst,
                               const float* __restrict__ wts,
                               const float* __restrict__ W,
                               const float* __restrict__ b,
                               float* __restrict__ out) {
    int t  = (int)(blockIdx.x * blockDim.x + threadIdx.x);
    int e0 = t * 4;
    if (e0 >= E_EDGES) return;   // E is a multiple of 4; full quads only

    // Batched independent loads (coalesced int4/float4)
    int4   s4 = *(const int4*)  (src + e0);
    int4   d4 = *(const int4*)  (dst + e0);
    float4 w4 = *(const float4*)(wts + e0);

    float wlin = __ldg(&W[2 * H_DIM]);
    float bias = __ldg(&b[0]);

    // 8 gathers in flight
    float a0 = g_d1[d4.x], a1 = g_d1[d4.y], a2 = g_d1[d4.z], a3 = g_d1[d4.w];
    float c0 = g_d2[s4.x], c1 = g_d2[s4.y], c2 = g_d2[s4.z], c3 = g_d2[s4.w];

    float v0 = a0 + c0 + fmaf(w4.x, wlin, bias);
    float v1 = a1 + c1 + fmaf(w4.y, wlin, bias);
    float v2 = a2 + c2 + fmaf(w4.z, wlin, bias);
    float v3 = a3 + c3 + fmaf(w4.w, wlin, bias);

    __stwt(&out[(size_t)d4.x * N_NODES + s4.x], v0);
    __stwt(&out[(size_t)d4.y * N_NODES + s4.y], v1);
    __stwt(&out[(size_t)d4.z * N_NODES + s4.z], v2);
    __stwt(&out[(size_t)d4.w * N_NODES + s4.w], v3);
}

// ---------------------------------------------------------------------------
// Launch. Input order (metadata): h, sources, dests, weights, W, b
// ---------------------------------------------------------------------------
extern "C" void kernel_launch(void* const* d_in, const int* in_sizes, int n_in,
                              void* d_out, int out_size) {
    const float* h       = (const float*)d_in[0];
    const int*   sources = (const int*)  d_in[1];
    const int*   dests   = (const int*)  d_in[2];
    const float* weights = (const float*)d_in[3];
    const float* W       = (const float*)d_in[4];
    const float* b       = (const float*)d_in[5];
    float*       out     = (float*)d_out;

    // 1) fused dots + fill
    {
        size_t n4   = ((size_t)N_NODES * N_NODES) / 4;  // 37,748,736 float4s
        int threads = 256;
        int blocks  = 148 * 16;                         // 2368 blocks
        dots_fill_kernel<<<blocks, threads>>>(h, W, (float4*)out, n4);
    }

    // 2) scatter edges, 4 edges/thread
    {
        int threads = 256;
        int quads   = E_EDGES / 4;                      // 98304
        int blocks  = (quads + threads - 1) / threads;  // 384
        scatter_kernel<<<blocks, threads>>>(sources, dests, weights, W, b, out);
    }
}